// round 8
// baseline (speedup 1.0000x reference)
#include <cuda_runtime.h>
#include <stdint.h>

// BasedKernel feature map, d=16:
//   out[row, 0]        = 1
//   out[row, 1..16]    = x[row, j-1] * 0.5
//   out[row, 17+idx]   = x[row, idx>>4] * x[row, idx&15] * SC2,  idx = 0..255
//
// R8: R4's spill-free phase 1 (one-value-per-lane x, hoisted-shfl quadratic,
// smem staging) + aligned float4 LDS->STG flush instead of TMA. Rationale:
// R4's only structural stall is the blocking cp.async.bulk.wait_group tail
// holding each CTA until TMA drains its smem; STG retires into the memory
// pipeline and the CTA exits immediately, pipelining CTA turnover. The STG
// flush was never tested without R1-R3's hidden local-memory spill.

#define SC2 0.17677669529663687f

#define ROWS_PER_BLOCK 8
#define THREADS        256
#define FLOATS_PER_BLOCK (ROWS_PER_BLOCK * 273)      // 2184
#define VEC4_PER_BLOCK   (FLOATS_PER_BLOCK / 4)      // 546

__global__ void __launch_bounds__(THREADS, 8)
based_feature_kernel(const float* __restrict__ x,
                     float* __restrict__ out)
{
    __shared__ __align__(16) float buf[FLOATS_PER_BLOCK];

    const int tid  = threadIdx.x;
    const int warp = tid >> 5;                 // 0..7 = local row
    const int lane = tid & 31;
    const int hi   = lane >> 4;                // 0 or 1
    const int row  = blockIdx.x * ROWS_PER_BLOCK + warp;

    // ---- Phase 1: one row per warp, x resident one-value-per-lane ----
    const float* xr = x + (size_t)row * 16;
    float v = (lane < 16) ? __ldg(xr + lane) : 0.0f;

    float* o = buf + warp * 273;

    // Convergent shfl first (full warp participates).
    const float b2 = __shfl_sync(0xffffffffu, v, lane & 15) * SC2;  // k-operand

    // Header (shfl-free, predicated stores only):
    if (lane < 16) o[1 + lane] = v * 0.5f;
    if (lane == 16) o[0] = 1.0f;

    // Quadratic: idx = 32m + lane, i = 2m + hi, k = lane&15.
#pragma unroll
    for (int m = 0; m < 8; ++m) {
        const float a = __shfl_sync(0xffffffffu, v, 2 * m + hi);
        o[17 + 32 * m + lane] = a * b2;
    }

    __syncthreads();

    // ---- Phase 2: aligned vectorized flush, 546 float4 per block ----
    // Block base byte = blockIdx * 8736, 8736 % 16 == 0 -> float4-aligned.
    // 546 = 2*256 + 34: two full rounds + predicated tail.
    const float4* s4 = reinterpret_cast<const float4*>(buf);
    float4* g4 = reinterpret_cast<float4*>(out + (size_t)blockIdx.x * FLOATS_PER_BLOCK);

    g4[tid]       = s4[tid];
    g4[tid + 256] = s4[tid + 256];
    if (tid < VEC4_PER_BLOCK - 512)
        g4[tid + 512] = s4[tid + 512];
}

extern "C" void kernel_launch(void* const* d_in, const int* in_sizes, int n_in,
                              void* d_out, int out_size)
{
    const float* x = (const float*)d_in[0];
    float* out = (float*)d_out;

    const int n_rows = in_sizes[0] / 16;              // 262144
    const int blocks = n_rows / ROWS_PER_BLOCK;       // 32768 (exact)

    based_feature_kernel<<<blocks, THREADS>>>(x, out);
}

// round 9
// speedup vs baseline: 1.1955x; 1.1955x over previous
#include <cuda_runtime.h>
#include <stdint.h>

// BasedKernel feature map, d=16:
//   out[row, 0]        = 1
//   out[row, 1..16]    = x[row, j-1] * 0.5
//   out[row, 17+idx]   = x[row, idx>>4] * x[row, idx&15] * SC2,  idx = 0..255
//
// R9: R4 (best: 45.7us ncu, DRAM 67%) + minimal 2-tile double buffer.
// Compute buf0 -> sync -> issue TMA0 (no wait) -> compute buf1 (overlaps
// TMA0 drain) -> sync -> issue TMA1 -> single wait. Blocking TMA tail paid
// once per 2 tiles; no persistent loop, no extra syncs (R7's mistake).

#define SC2 0.17677669529663687f

#define ROWS_PER_TILE 8
#define THREADS       256
#define FLOATS_PER_TILE (ROWS_PER_TILE * 273)        // 2184
#define BYTES_PER_TILE  (FLOATS_PER_TILE * 4)        // 8736, multiple of 16

__device__ __forceinline__ void compute_tile(const float* __restrict__ x,
                                             float* __restrict__ o,
                                             int row, int lane, int hi)
{
    const float* xr = x + (size_t)row * 16;
    float v = (lane < 16) ? __ldg(xr + lane) : 0.0f;

    // Convergent shfl first (full warp participates).
    const float b2 = __shfl_sync(0xffffffffu, v, lane & 15) * SC2;  // k-operand

    // Header (shfl-free, predicated stores only).
    if (lane < 16) o[1 + lane] = v * 0.5f;
    if (lane == 16) o[0] = 1.0f;

    // Quadratic: idx = 32m + lane, i = 2m + hi, k = lane&15.
#pragma unroll
    for (int m = 0; m < 8; ++m) {
        const float a = __shfl_sync(0xffffffffu, v, 2 * m + hi);
        o[17 + 32 * m + lane] = a * b2;
    }
}

__device__ __forceinline__ void issue_flush(const float* sbuf, float* g)
{
    uint32_t saddr;
    asm volatile(
        "{ .reg .u64 t; cvta.to.shared.u64 t, %1; cvt.u32.u64 %0, t; }"
        : "=r"(saddr) : "l"(sbuf));
    asm volatile("fence.proxy.async.shared::cta;" ::: "memory");
    asm volatile(
        "cp.async.bulk.global.shared::cta.bulk_group [%0], [%1], %2;"
        :: "l"(g), "r"(saddr), "n"(BYTES_PER_TILE) : "memory");
    asm volatile("cp.async.bulk.commit_group;" ::: "memory");
}

__global__ void __launch_bounds__(THREADS, 8)
based_feature_kernel(const float* __restrict__ x,
                     float* __restrict__ out)
{
    __shared__ __align__(16) float buf[2][FLOATS_PER_TILE];

    const int tid  = threadIdx.x;
    const int warp = tid >> 5;                 // 0..7 = local row within tile
    const int lane = tid & 31;
    const int hi   = lane >> 4;                // 0 or 1

    const int row0 = blockIdx.x * (2 * ROWS_PER_TILE) + warp;   // tile 0 row
    float* gbase = out + (size_t)blockIdx.x * (2 * FLOATS_PER_TILE);

    // ---- tile 0 ----
    compute_tile(x, buf[0] + warp * 273, row0, lane, hi);
    __syncthreads();
    if (tid == 0) issue_flush(buf[0], gbase);

    // ---- tile 1 (compute overlaps TMA drain of tile 0) ----
    compute_tile(x, buf[1] + warp * 273, row0 + ROWS_PER_TILE, lane, hi);
    __syncthreads();
    if (tid == 0) {
        issue_flush(buf[1], gbase + FLOATS_PER_TILE);
        // Drain both flushes before CTA exit (smem lifetime).
        asm volatile("cp.async.bulk.wait_group.read 0;" ::: "memory");
    }
}

extern "C" void kernel_launch(void* const* d_in, const int* in_sizes, int n_in,
                              void* d_out, int out_size)
{
    const float* x = (const float*)d_in[0];
    float* out = (float*)d_out;

    const int n_rows = in_sizes[0] / 16;                   // 262144
    const int blocks = n_rows / (2 * ROWS_PER_TILE);       // 16384 (exact)

    based_feature_kernel<<<blocks, THREADS>>>(x, out);
}